// round 2
// baseline (speedup 1.0000x reference)
#include <cuda_runtime.h>

#define B_   16384
#define L_   50
#define TILE 64            // batch rows per CTA
#define HS   68            // hsT stride (floats), 16B-aligned (68*4=272)
#define WS   132           // wsT stride (floats), 16B-aligned

// ---------------------------------------------------------------------------
// Fused: masked gather-sum into smem tile (k-major), then 64x128x128 GEMM
// out = his @ W^T + b.  Grid = 256 CTAs x 256 threads, ~100KB dynamic smem
// -> 2 CTAs/SM.
// ---------------------------------------------------------------------------
__global__ __launch_bounds__(256) void fused_kernel(
    const int*    __restrict__ entities,
    const int*    __restrict__ history,
    const int*    __restrict__ hist_len,
    const float4* __restrict__ embv,   // emb as float4, row stride 32
    const float4* __restrict__ Wv,     // W as float4, row stride 32
    const float*  __restrict__ bias,
    float*        __restrict__ out)
{
    extern __shared__ float sm[];
    float* hsT = sm;                   // [128][HS]  k-major, i inner
    float* wsT = sm + 128 * HS;        // [128][WS]  k-major, j inner

    __shared__ int sh_idx[8][52];

    const int tid  = threadIdx.x;
    const int warp = tid >> 5;
    const int lane = tid & 31;
    const int row0 = blockIdx.x * TILE;

    // ---- Stage W transposed (64KB from L2/DRAM, once per CTA) ----
    for (int t = tid; t < 128 * 32; t += 256) {
        const int i  = t >> 5;
        const int kv = t & 31;
        float4 w = Wv[i * 32 + kv];
        wsT[(kv * 4 + 0) * WS + i] = w.x;
        wsT[(kv * 4 + 1) * WS + i] = w.y;
        wsT[(kv * 4 + 2) * WS + i] = w.z;
        wsT[(kv * 4 + 3) * WS + i] = w.w;
    }

    // ---- Gather: each warp owns 8 consecutive tile rows ----
    for (int rr = 0; rr < 8; rr++) {
        const int r = warp * 8 + rr;
        const int b = row0 + r;
        const int n = (int)hist_len[b];

        if (lane < n)      sh_idx[warp][lane]      = history[b * L_ + lane];
        if (lane + 32 < n) sh_idx[warp][lane + 32] = history[b * L_ + lane + 32];
        __syncwarp();

        float4 a0 = make_float4(0.f, 0.f, 0.f, 0.f);
        float4 a1 = a0, a2 = a0, a3 = a0;

        int l = 0;
        for (; l + 4 <= n; l += 4) {
            const long i0 = sh_idx[warp][l + 0];
            const long i1 = sh_idx[warp][l + 1];
            const long i2 = sh_idx[warp][l + 2];
            const long i3 = sh_idx[warp][l + 3];
            float4 v0 = __ldg(&embv[i0 * 32 + lane]);
            float4 v1 = __ldg(&embv[i1 * 32 + lane]);
            float4 v2 = __ldg(&embv[i2 * 32 + lane]);
            float4 v3 = __ldg(&embv[i3 * 32 + lane]);
            a0.x += v0.x; a0.y += v0.y; a0.z += v0.z; a0.w += v0.w;
            a1.x += v1.x; a1.y += v1.y; a1.z += v1.z; a1.w += v1.w;
            a2.x += v2.x; a2.y += v2.y; a2.z += v2.z; a2.w += v2.w;
            a3.x += v3.x; a3.y += v3.y; a3.z += v3.z; a3.w += v3.w;
        }
        for (; l < n; l++) {
            const long i0 = sh_idx[warp][l];
            float4 v0 = __ldg(&embv[i0 * 32 + lane]);
            a0.x += v0.x; a0.y += v0.y; a0.z += v0.z; a0.w += v0.w;
        }

        float4 acc;
        acc.x = (a0.x + a1.x) + (a2.x + a3.x);
        acc.y = (a0.y + a1.y) + (a2.y + a3.y);
        acc.z = (a0.z + a1.z) + (a2.z + a3.z);
        acc.w = (a0.w + a1.w) + (a2.w + a3.w);

        if (n == 0)
            acc = __ldg(&embv[(long)entities[b] * 32 + lane]);

        // scatter into k-major tile: lane covers k = 4*lane .. 4*lane+3
        hsT[(4 * lane + 0) * HS + r] = acc.x;
        hsT[(4 * lane + 1) * HS + r] = acc.y;
        hsT[(4 * lane + 2) * HS + r] = acc.z;
        hsT[(4 * lane + 3) * HS + r] = acc.w;
        __syncwarp();   // protect sh_idx reuse next iteration
    }
    __syncthreads();

    // ---- GEMM: 64x128 tile, 4i x 8j per thread ----
    const int tx = tid & 15;            // j
    const int ty = tid >> 4;            // i
    const int j0 = tx * 8;
    const int i0 = ty * 4;

    float acc[4][8];
#pragma unroll
    for (int ii = 0; ii < 4; ii++)
#pragma unroll
        for (int jj = 0; jj < 8; jj++)
            acc[ii][jj] = 0.f;

#pragma unroll 8
    for (int k = 0; k < 128; k++) {
        float a[4], bb[8];
        *(float4*)&a[0]  = *(const float4*)&hsT[k * HS + i0];
        *(float4*)&bb[0] = *(const float4*)&wsT[k * WS + j0];
        *(float4*)&bb[4] = *(const float4*)&wsT[k * WS + j0 + 4];
#pragma unroll
        for (int ii = 0; ii < 4; ii++)
#pragma unroll
            for (int jj = 0; jj < 8; jj++)
                acc[ii][jj] = fmaf(a[ii], bb[jj], acc[ii][jj]);
    }

    float bj[8];
    *(float4*)&bj[0] = ((const float4*)bias)[tx * 2 + 0];
    *(float4*)&bj[4] = ((const float4*)bias)[tx * 2 + 1];

#pragma unroll
    for (int ii = 0; ii < 4; ii++) {
        float4 o0, o1;
        o0.x = acc[ii][0] + bj[0]; o0.y = acc[ii][1] + bj[1];
        o0.z = acc[ii][2] + bj[2]; o0.w = acc[ii][3] + bj[3];
        o1.x = acc[ii][4] + bj[4]; o1.y = acc[ii][5] + bj[5];
        o1.z = acc[ii][6] + bj[6]; o1.w = acc[ii][7] + bj[7];
        float* orow = out + (long)(row0 + i0 + ii) * 128 + j0;
        *(float4*)&orow[0] = o0;
        *(float4*)&orow[4] = o1;
    }
}

// ---------------------------------------------------------------------------
extern "C" void kernel_launch(void* const* d_in, const int* in_sizes, int n_in,
                              void* d_out, int out_size)
{
    const int*   entities = (const int*)d_in[0];
    const int*   history  = (const int*)d_in[1];
    const int*   hist_len = (const int*)d_in[2];
    const float* emb      = (const float*)d_in[3];
    const float* W        = (const float*)d_in[4];
    const float* bias     = (const float*)d_in[5];
    float*       out      = (float*)d_out;

    const size_t smem = (size_t)(128 * HS + 128 * WS) * sizeof(float);
    cudaFuncSetAttribute(fused_kernel,
                         cudaFuncAttributeMaxDynamicSharedMemorySize,
                         (int)smem);
    fused_kernel<<<B_ / TILE, 256, smem>>>(
        entities, history, hist_len,
        (const float4*)emb, (const float4*)W, bias, out);
}

// round 3
// speedup vs baseline: 1.1164x; 1.1164x over previous
#include <cuda_runtime.h>

#define B_  16384
#define L_  50
#define D_  128
#define TILE 64          // batch rows per linear CTA
#define HS   68          // hsT stride (floats), 16B aligned
#define WS   132         // wsT stride (floats), 16B aligned

// 8 MB scratch for the pooled history embedding [B, D]
__device__ float g_his[B_ * D_];

// ---------------------------------------------------------------------------
// Kernel 1: masked gather-sum. One warp per batch row, float4 per lane.
// (identical to R1 — measured ~5.4 TB/s effective, DRAM-random bound)
// ---------------------------------------------------------------------------
__global__ __launch_bounds__(256) void gather_kernel(
    const int*    __restrict__ entities,
    const int*    __restrict__ history,
    const int*    __restrict__ hist_len,
    const float4* __restrict__ embv)
{
    const int warp = threadIdx.x >> 5;
    const int lane = threadIdx.x & 31;
    const int b    = (blockIdx.x << 3) + warp;

    __shared__ int sh_idx[8][52];

    const int n = hist_len[b];
    for (int l = lane; l < n; l += 32)
        sh_idx[warp][l] = history[b * L_ + l];
    __syncwarp();

    float4 a0 = make_float4(0.f, 0.f, 0.f, 0.f);
    float4 a1 = a0, a2 = a0, a3 = a0;

    int l = 0;
    for (; l + 4 <= n; l += 4) {
        const long i0 = sh_idx[warp][l + 0];
        const long i1 = sh_idx[warp][l + 1];
        const long i2 = sh_idx[warp][l + 2];
        const long i3 = sh_idx[warp][l + 3];
        float4 v0 = __ldg(&embv[i0 * 32 + lane]);
        float4 v1 = __ldg(&embv[i1 * 32 + lane]);
        float4 v2 = __ldg(&embv[i2 * 32 + lane]);
        float4 v3 = __ldg(&embv[i3 * 32 + lane]);
        a0.x += v0.x; a0.y += v0.y; a0.z += v0.z; a0.w += v0.w;
        a1.x += v1.x; a1.y += v1.y; a1.z += v1.z; a1.w += v1.w;
        a2.x += v2.x; a2.y += v2.y; a2.z += v2.z; a2.w += v2.w;
        a3.x += v3.x; a3.y += v3.y; a3.z += v3.z; a3.w += v3.w;
    }
    for (; l < n; l++) {
        const long i0 = sh_idx[warp][l];
        float4 v0 = __ldg(&embv[i0 * 32 + lane]);
        a0.x += v0.x; a0.y += v0.y; a0.z += v0.z; a0.w += v0.w;
    }

    float4 acc;
    acc.x = (a0.x + a1.x) + (a2.x + a3.x);
    acc.y = (a0.y + a1.y) + (a2.y + a3.y);
    acc.z = (a0.z + a1.z) + (a2.z + a3.z);
    acc.w = (a0.w + a1.w) + (a2.w + a3.w);

    if (n == 0)
        acc = __ldg(&embv[(long)entities[b] * 32 + lane]);

    ((float4*)g_his)[b * 32 + lane] = acc;
}

// ---------------------------------------------------------------------------
// Kernel 2: out = his @ W^T + bias.  64x128 tile per CTA (100KB smem ->
// 2 CTAs/SM, 16 warps), 256 threads, 4i x 8j register microtile.
// ---------------------------------------------------------------------------
__global__ __launch_bounds__(256) void linear_kernel(
    const float* __restrict__ W,
    const float* __restrict__ bias,
    float*       __restrict__ out)
{
    extern __shared__ float sm[];
    float* hsT = sm;                 // [128][HS]  k-major, i inner (64 used)
    float* wsT = sm + 128 * HS;      // [128][WS]  k-major, j inner

    const int tid  = threadIdx.x;
    const int row0 = blockIdx.x * TILE;

    const float4* hisv = (const float4*)g_his;
    const float4* Wv   = (const float4*)W;

    // Stage W transposed: 128 rows x 32 float4
    for (int t = tid; t < 128 * 32; t += 256) {
        const int i  = t >> 5;
        const int kv = t & 31;
        float4 w = Wv[(long)i * 32 + kv];
        wsT[(kv * 4 + 0) * WS + i] = w.x;
        wsT[(kv * 4 + 1) * WS + i] = w.y;
        wsT[(kv * 4 + 2) * WS + i] = w.z;
        wsT[(kv * 4 + 3) * WS + i] = w.w;
    }
    // Stage his tile transposed: 64 rows x 32 float4
    for (int t = tid; t < TILE * 32; t += 256) {
        const int i  = t >> 5;
        const int kv = t & 31;
        float4 v = hisv[(long)(row0 + i) * 32 + kv];
        hsT[(kv * 4 + 0) * HS + i] = v.x;
        hsT[(kv * 4 + 1) * HS + i] = v.y;
        hsT[(kv * 4 + 2) * HS + i] = v.z;
        hsT[(kv * 4 + 3) * HS + i] = v.w;
    }
    __syncthreads();

    const int tx = tid & 15;        // j
    const int ty = tid >> 4;        // i
    const int j0 = tx * 8;
    const int i0 = ty * 4;

    float acc[4][8];
#pragma unroll
    for (int ii = 0; ii < 4; ii++)
#pragma unroll
        for (int jj = 0; jj < 8; jj++)
            acc[ii][jj] = 0.f;

#pragma unroll 8
    for (int k = 0; k < 128; k++) {
        float a[4], bb[8];
        *(float4*)&a[0]  = *(const float4*)&hsT[k * HS + i0];
        *(float4*)&bb[0] = *(const float4*)&wsT[k * WS + j0];
        *(float4*)&bb[4] = *(const float4*)&wsT[k * WS + j0 + 4];
#pragma unroll
        for (int ii = 0; ii < 4; ii++)
#pragma unroll
            for (int jj = 0; jj < 8; jj++)
                acc[ii][jj] = fmaf(a[ii], bb[jj], acc[ii][jj]);
    }

    float bj[8];
    *(float4*)&bj[0] = ((const float4*)bias)[tx * 2 + 0];
    *(float4*)&bj[4] = ((const float4*)bias)[tx * 2 + 1];

#pragma unroll
    for (int ii = 0; ii < 4; ii++) {
        float4 o0, o1;
        o0.x = acc[ii][0] + bj[0]; o0.y = acc[ii][1] + bj[1];
        o0.z = acc[ii][2] + bj[2]; o0.w = acc[ii][3] + bj[3];
        o1.x = acc[ii][4] + bj[4]; o1.y = acc[ii][5] + bj[5];
        o1.z = acc[ii][6] + bj[6]; o1.w = acc[ii][7] + bj[7];
        float* orow = out + (long)(row0 + i0 + ii) * 128 + j0;
        *(float4*)&orow[0] = o0;
        *(float4*)&orow[4] = o1;
    }
}

// ---------------------------------------------------------------------------
extern "C" void kernel_launch(void* const* d_in, const int* in_sizes, int n_in,
                              void* d_out, int out_size)
{
    const int*   entities = (const int*)d_in[0];
    const int*   history  = (const int*)d_in[1];
    const int*   hist_len = (const int*)d_in[2];
    const float* emb      = (const float*)d_in[3];
    const float* W        = (const float*)d_in[4];
    const float* bias     = (const float*)d_in[5];
    float*       out      = (float*)d_out;

    gather_kernel<<<B_ / 8, 256>>>(entities, history, hist_len,
                                   (const float4*)emb);

    const size_t smem = (size_t)(128 * HS + 128 * WS) * sizeof(float);
    cudaFuncSetAttribute(linear_kernel,
                         cudaFuncAttributeMaxDynamicSharedMemorySize,
                         (int)smem);
    linear_kernel<<<B_ / TILE, 256, smem>>>(W, bias, out);
}

// round 4
// speedup vs baseline: 1.3950x; 1.2495x over previous
#include <cuda_runtime.h>
#include <cstdint>

#define B_  16384
#define L_  50
#define D_  128
#define ST  132        // smem row stride in floats (132*4=528B, 16B aligned)

// 8 MB scratch for the pooled history embedding [B, D]
__device__ float g_his[B_ * D_];

// ---------------------------------------------------------------------------
// Kernel 1: masked gather-sum. One warp per batch row, float4 per lane.
// ---------------------------------------------------------------------------
__global__ __launch_bounds__(256) void gather_kernel(
    const int*    __restrict__ entities,
    const int*    __restrict__ history,
    const int*    __restrict__ hist_len,
    const float4* __restrict__ embv)
{
    const int warp = threadIdx.x >> 5;
    const int lane = threadIdx.x & 31;
    const int b    = (blockIdx.x << 3) + warp;

    __shared__ int sh_idx[8][52];

    const int n = hist_len[b];
    for (int l = lane; l < n; l += 32)
        sh_idx[warp][l] = history[b * L_ + l];
    __syncwarp();

    float4 a0 = make_float4(0.f, 0.f, 0.f, 0.f);
    float4 a1 = a0, a2 = a0, a3 = a0;

    int l = 0;
    for (; l + 4 <= n; l += 4) {
        const long i0 = sh_idx[warp][l + 0];
        const long i1 = sh_idx[warp][l + 1];
        const long i2 = sh_idx[warp][l + 2];
        const long i3 = sh_idx[warp][l + 3];
        float4 v0 = __ldg(&embv[i0 * 32 + lane]);
        float4 v1 = __ldg(&embv[i1 * 32 + lane]);
        float4 v2 = __ldg(&embv[i2 * 32 + lane]);
        float4 v3 = __ldg(&embv[i3 * 32 + lane]);
        a0.x += v0.x; a0.y += v0.y; a0.z += v0.z; a0.w += v0.w;
        a1.x += v1.x; a1.y += v1.y; a1.z += v1.z; a1.w += v1.w;
        a2.x += v2.x; a2.y += v2.y; a2.z += v2.z; a2.w += v2.w;
        a3.x += v3.x; a3.y += v3.y; a3.z += v3.z; a3.w += v3.w;
    }
    for (; l < n; l++) {
        const long i0 = sh_idx[warp][l];
        float4 v0 = __ldg(&embv[i0 * 32 + lane]);
        a0.x += v0.x; a0.y += v0.y; a0.z += v0.z; a0.w += v0.w;
    }

    float4 acc;
    acc.x = (a0.x + a1.x) + (a2.x + a3.x);
    acc.y = (a0.y + a1.y) + (a2.y + a3.y);
    acc.z = (a0.z + a1.z) + (a2.z + a3.z);
    acc.w = (a0.w + a1.w) + (a2.w + a3.w);

    if (n == 0)
        acc = __ldg(&embv[(long)entities[b] * 32 + lane]);

    ((float4*)g_his)[b * 32 + lane] = acc;
}

// ---------------------------------------------------------------------------
// TF32 helpers
// ---------------------------------------------------------------------------
__device__ __forceinline__ uint32_t f2tf32(float x) {
    uint32_t r;
    asm("cvt.rna.tf32.f32 %0, %1;" : "=r"(r) : "f"(x));
    return r;
}
__device__ __forceinline__ void split_tf32(float x, uint32_t& hi, uint32_t& lo) {
    hi = f2tf32(x);
    lo = f2tf32(x - __uint_as_float(hi));
}
__device__ __forceinline__ void mma_tf32(float c[4], const uint32_t a[4],
                                         uint32_t b0, uint32_t b1) {
    asm volatile(
        "mma.sync.aligned.m16n8k8.row.col.f32.tf32.tf32.f32 "
        "{%0,%1,%2,%3}, {%4,%5,%6,%7}, {%8,%9}, {%0,%1,%2,%3};"
        : "+f"(c[0]), "+f"(c[1]), "+f"(c[2]), "+f"(c[3])
        : "r"(a[0]), "r"(a[1]), "r"(a[2]), "r"(a[3]), "r"(b0), "r"(b1));
}

// ---------------------------------------------------------------------------
// Kernel 2: out = his @ W^T + bias via 3-pass split-TF32 mma.sync.
// CTA = 128x128 tile, 8 warps; warp = 32 rows x 64 cols.
// smem: his tile [128][ST] raw fp32, W hi/lo [128][ST] each (tf32 patterns).
// ---------------------------------------------------------------------------
__global__ __launch_bounds__(256) void linear_kernel(
    const float4* __restrict__ Wv,
    const float*  __restrict__ bias,
    float*        __restrict__ out)
{
    extern __shared__ float sm[];
    float* hs  = sm;                 // [128][ST] his rows (fp32)
    float* whi = sm + 128 * ST;      // [128][ST] W hi (tf32 bit patterns)
    float* wlo = sm + 2 * 128 * ST;  // [128][ST] W lo

    const int tid  = threadIdx.x;
    const int lane = tid & 31;
    const int warp = tid >> 5;
    const int gq   = lane >> 2;      // group id 0..7
    const int tq   = lane & 3;       // thread-in-group 0..3
    const int wm   = warp >> 1;      // 0..3 (row group)
    const int wn   = warp & 1;       // 0..1 (col group)
    const int row0 = blockIdx.x * 128;

    const float4* hisv = (const float4*)g_his;

    // Stage his tile (raw) and W split hi/lo.
    for (int t = tid; t < 128 * 32; t += 256) {
        const int r  = t >> 5;
        const int kv = t & 31;
        float4 v = hisv[(long)(row0 + r) * 32 + kv];
        ((float4*)(hs + r * ST))[kv] = v;

        float4 w = Wv[(long)r * 32 + kv];
        uint32_t h0, l0, h1, l1, h2, l2, h3, l3;
        split_tf32(w.x, h0, l0);
        split_tf32(w.y, h1, l1);
        split_tf32(w.z, h2, l2);
        split_tf32(w.w, h3, l3);
        float4 wh, wl;
        wh.x = __uint_as_float(h0); wh.y = __uint_as_float(h1);
        wh.z = __uint_as_float(h2); wh.w = __uint_as_float(h3);
        wl.x = __uint_as_float(l0); wl.y = __uint_as_float(l1);
        wl.z = __uint_as_float(l2); wl.w = __uint_as_float(l3);
        ((float4*)(whi + r * ST))[kv] = wh;
        ((float4*)(wlo + r * ST))[kv] = wl;
    }
    __syncthreads();

    // Accumulators initialized with bias (per output column).
    float c[2][8][4];
#pragma unroll
    for (int n = 0; n < 8; n++) {
        const int col = wn * 64 + n * 8 + 2 * tq;
        const float b0 = __ldg(&bias[col]);
        const float b1 = __ldg(&bias[col + 1]);
#pragma unroll
        for (int m = 0; m < 2; m++) {
            c[m][n][0] = b0; c[m][n][1] = b1;
            c[m][n][2] = b0; c[m][n][3] = b1;
        }
    }

#pragma unroll
    for (int kt = 0; kt < 16; kt++) {
        const int k0 = kt * 8;

        // A fragments (his), split hi/lo in registers.
        uint32_t ahi[2][4], alo[2][4];
#pragma unroll
        for (int m = 0; m < 2; m++) {
            const int r = wm * 32 + m * 16 + gq;
            float x0 = hs[r * ST + k0 + tq];
            float x1 = hs[(r + 8) * ST + k0 + tq];
            float x2 = hs[r * ST + k0 + tq + 4];
            float x3 = hs[(r + 8) * ST + k0 + tq + 4];
            split_tf32(x0, ahi[m][0], alo[m][0]);
            split_tf32(x1, ahi[m][1], alo[m][1]);
            split_tf32(x2, ahi[m][2], alo[m][2]);
            split_tf32(x3, ahi[m][3], alo[m][3]);
        }

#pragma unroll
        for (int n = 0; n < 8; n++) {
            const int j = wn * 64 + n * 8 + gq;    // output col = W row
            uint32_t bh0 = __float_as_uint(whi[j * ST + k0 + tq]);
            uint32_t bh1 = __float_as_uint(whi[j * ST + k0 + tq + 4]);
            uint32_t bl0 = __float_as_uint(wlo[j * ST + k0 + tq]);
            uint32_t bl1 = __float_as_uint(wlo[j * ST + k0 + tq + 4]);
#pragma unroll
            for (int m = 0; m < 2; m++) {
                mma_tf32(c[m][n], ahi[m], bh0, bh1);   // Ah*Bh
                mma_tf32(c[m][n], ahi[m], bl0, bl1);   // Ah*Bl
                mma_tf32(c[m][n], alo[m], bh0, bh1);   // Al*Bh
            }
        }
    }

    // Epilogue: store C fragments.
#pragma unroll
    for (int m = 0; m < 2; m++) {
        const int r = row0 + wm * 32 + m * 16 + gq;
#pragma unroll
        for (int n = 0; n < 8; n++) {
            const int col = wn * 64 + n * 8 + 2 * tq;
            float2 v0 = make_float2(c[m][n][0], c[m][n][1]);
            float2 v1 = make_float2(c[m][n][2], c[m][n][3]);
            *(float2*)&out[(long)r * 128 + col]       = v0;
            *(float2*)&out[(long)(r + 8) * 128 + col] = v1;
        }
    }
}

// ---------------------------------------------------------------------------
extern "C" void kernel_launch(void* const* d_in, const int* in_sizes, int n_in,
                              void* d_out, int out_size)
{
    const int*   entities = (const int*)d_in[0];
    const int*   history  = (const int*)d_in[1];
    const int*   hist_len = (const int*)d_in[2];
    const float* emb      = (const float*)d_in[3];
    const float* W        = (const float*)d_in[4];
    const float* bias     = (const float*)d_in[5];
    float*       out      = (float*)d_out;

    gather_kernel<<<B_ / 8, 256>>>(entities, history, hist_len,
                                   (const float4*)emb);

    const size_t smem = (size_t)3 * 128 * ST * sizeof(float);   // ~203 KB
    cudaFuncSetAttribute(linear_kernel,
                         cudaFuncAttributeMaxDynamicSharedMemorySize,
                         (int)smem);
    linear_kernel<<<B_ / 128, 256, smem>>>((const float4*)W, bias, out);
}